// round 15
// baseline (speedup 1.0000x reference)
#include <cuda_runtime.h>
#include <cstdint>

#define B_  2048
#define T_  336
#define F_  10
#define H1_ 70
#define H2_ 21
#define D1_ 30
#define D2_ 20

typedef unsigned long long u64;

// ---------------- scratch (__device__ globals; no allocations) ----------------
__device__ float g_xT [(size_t)T_ * B_ * F_];          // x transposed [T][B][10]
__device__ float g_h1 [(size_t)T_ * B_ * (2*H1_)];     // layer1 out   [T][B][140]
__device__ float g_xg2[(size_t)T_ * B_ * (8*H2_)];     // layer2 input gates [T][B][168] (gate-interleaved)
__device__ float g_h2 [(size_t)T_ * B_ * (2*H2_)];     // layer2 out   [T][B][42]
__device__ float g_w2t[140 * 168];                     // W2_ih^T packed, both dirs, gate-interleaved
__device__ float g_b2 [168];

// ---------------- packed f32x2 fma ----------------
__device__ __forceinline__ u64 fma2_(u64 a, u64 b, u64 c) {
    u64 d;
    asm("fma.rn.f32x2 %0, %1, %2, %3;" : "=l"(d) : "l"(a), "l"(b), "l"(c));
    return d;
}

// ---------------- activations (accurate fast-math, ~1e-6 rel) ----------------
__device__ __forceinline__ float fsigm(float x) {
    return __fdividef(1.f, 1.f + __expf(-x));
}
__device__ __forceinline__ float ftanh_(float x) {
    return 1.f - 2.f * __fdividef(1.f, 1.f + __expf(2.f * x));
}

// ---------------- transpose x: [B][T][F] -> [T][B][F] (split in halves) ----------------
__global__ void transpose_x(const float* __restrict__ x, int base) {
    int gid = base + blockIdx.x * blockDim.x + threadIdx.x;
    if (gid < B_ * T_ * F_) {
        int f = gid % F_;
        int t = (gid / F_) % T_;
        int b = gid / (F_ * T_);
        g_xT[((size_t)t * B_ + b) * F_ + f] = x[gid];
    }
}

// ---------------- prep: transpose layer-2 input weights to k-major, gate-interleaved ----------------
__global__ void prep_w2(const float* __restrict__ wf, const float* __restrict__ wb,
                        const float* __restrict__ bfi, const float* __restrict__ bfh,
                        const float* __restrict__ bbi, const float* __restrict__ bbh) {
    int i = blockIdx.x * blockDim.x + threadIdx.x;
    if (i < 168 * 140) {
        int jj = i / 140;
        int k  = i % 140;
        int dir = jj / 84, r = jj % 84;
        int h = r / 4, gate = r % 4;
        int j = gate * H2_ + h;
        const float* w = dir ? wb : wf;
        g_w2t[k * 168 + jj] = w[j * 140 + k];
    }
    if (i < 168) {
        int dir = i / 84, r = i % 84;
        int h = r / 4, gate = r % 4;
        int j = gate * H2_ + h;
        g_b2[i] = dir ? (bbi[j] + bbh[j]) : (bfi[j] + bfh[j]);
    }
}

// ================= layer 1: fused-input recurrent LSTM, crossbar-lean shape =================
// BB=28 -> 74 x 2 = 148 blocks (one/SM). 432 threads = 3 K-teams x (2 SG x 72 chunks), TB=14.
// K padded to 84 (row 80 = bias via a=1; 81-83 zero) -> 3 even teams of 28 k.
// W-wf/step 2880->1512, a-wf 5040->2646 vs R10 shape; FMA +5% (pad).
__global__ __launch_bounds__(432, 1)
void lstm1_kernel(const float* __restrict__ Wih_f, const float* __restrict__ Whh_f,
                  const float* __restrict__ bih_f, const float* __restrict__ bhh_f,
                  const float* __restrict__ Wih_b, const float* __restrict__ Whh_b,
                  const float* __restrict__ bih_b, const float* __restrict__ bhh_b)
{
    constexpr int I = 10, H = 70, KPAD = 84, KP2 = 86, G = 280, GP = 288;
    constexpr int NJC = 72, TB = 14, NTH = 432, KH = 28, BB = 28, NTEAM = 3;
    extern __shared__ float sm[];
    float* sW = sm;                      // [84][288] k-major, gate-interleaved (row 80 = bias)
    float* gP = sW + KPAD * GP;          // [3][28][288] partial gates
    float* aS = gP + NTEAM * BB * GP;    // [28][86] duplicated pairs (float2)
    float* cS = aS + BB * KP2 * 2;       // [28][70]

    const int dir = blockIdx.y;
    const float* Wih = dir ? Wih_b : Wih_f;
    const float* Whh = dir ? Whh_b : Whh_f;
    const float* bih = dir ? bih_b : bih_f;
    const float* bhh = dir ? bhh_b : bhh_f;
    const int b0  = blockIdx.x * BB;
    const int tid = threadIdx.x;

    for (int idx = tid; idx < KPAD * GP; idx += NTH) {
        int k = idx / GP, jj = idx % GP;
        float v = 0.f;
        if (jj < G) {
            int h = jj / 4, gate = jj % 4;
            int j = gate * H + h;
            if (k < I)        v = Wih[j * I + k];
            else if (k < 80)  v = Whh[j * H + (k - I)];
            else if (k == 80) v = bih[j] + bhh[j];
        }
        sW[idx] = v;
    }
    for (int idx = tid; idx < BB * KP2 * 2; idx += NTH) aS[idx] = 0.f;
    for (int idx = tid; idx < BB * H; idx += NTH) cS[idx] = 0.f;
    __syncthreads();
    if (tid < BB) ((float2*)aS)[tid * KP2 + 80] = make_float2(1.f, 1.f);   // bias lane

    const bool xp = tid < BB * I;
    const int xb0 = tid / I, xk0 = tid % I;
    const bool xval = xp && (b0 + xb0 < B_);   // tail-chunk guard
    const int ab0 = tid / H, ah0 = tid % H;

    const int ks = tid / 144;           // K-team 0..2
    const int r144 = tid - ks * 144;
    const int sg = r144 / NJC, jc = r144 % NJC;
    const int kbase = ks * KH;
    const u64* arow = ((const u64*)aS) + (size_t)(sg * TB) * KP2;
    const ulonglong2* sWp = (const ulonglong2*)sW;
    ulonglong2* gPd = ((ulonglong2*)(gP + ks * BB * GP));

    int t = dir ? (T_ - 1) : 0;
    const int tstep = dir ? -1 : 1;
    float xp0 = 0.f;
    if (xval) xp0 = g_xT[((size_t)t * B_ + b0) * I + tid];
    __syncthreads();

    for (int s = 0; s < T_; ++s, t += tstep) {
        if (xp) ((float2*)aS)[xb0 * KP2 + xk0] = make_float2(xp0, xp0);
        __syncthreads();
        if (xval && s + 1 < T_)
            xp0 = g_xT[((size_t)(t + tstep) * B_ + b0) * I + tid];

        // ---- packed matvec partial over k in [kbase, kbase+28) ----
        {
            ulonglong2 acc[TB];
            #pragma unroll
            for (int r = 0; r < TB; ++r) acc[r] = make_ulonglong2(0ull, 0ull);

            #pragma unroll 2
            for (int kk = 0; kk < KH; kk += 2) {
                const int k = kbase + kk;
                ulonglong2 w0 = sWp[k * NJC + jc];
                ulonglong2 w1 = sWp[(k + 1) * NJC + jc];
                #pragma unroll
                for (int r = 0; r < TB; ++r) {
                    ulonglong2 a = *(const ulonglong2*)(arow + r * KP2 + k);
                    acc[r].x = fma2_(a.x, w0.x, acc[r].x);
                    acc[r].y = fma2_(a.x, w0.y, acc[r].y);
                    acc[r].x = fma2_(a.y, w1.x, acc[r].x);
                    acc[r].y = fma2_(a.y, w1.y, acc[r].y);
                }
            }
            #pragma unroll
            for (int r = 0; r < TB; ++r) gPd[(sg * TB + r) * NJC + jc] = acc[r];
        }
        __syncthreads();

        // ---- gates: sum 3 partials (float4 each) + state update + h store ----
        {
            float* orow = g_h1 + ((size_t)t * B_ + b0) * (2 * H1_) + dir * H;
            int b = ab0, h = ah0;
            for (int e = tid; e < BB * H; e += NTH) {
                float4 q0 = ((const float4*)(gP + b * GP))[h];
                float4 q1 = ((const float4*)(gP + BB * GP + b * GP))[h];
                float4 q2 = ((const float4*)(gP + 2 * BB * GP + b * GP))[h];
                float gi = q0.x + q1.x + q2.x;
                float gf = q0.y + q1.y + q2.y;
                float gg = q0.z + q1.z + q2.z;
                float go = q0.w + q1.w + q2.w;
                float c = fsigm(gf) * cS[e] + fsigm(gi) * ftanh_(gg);
                cS[e] = c;
                float hn = fsigm(go) * ftanh_(c);
                ((float2*)aS)[b * KP2 + I + h] = make_float2(hn, hn);
                if (b0 + b < B_) orow[b * (2 * H1_) + h] = hn;
                b += 6; h += 12; if (h >= H) { h -= H; ++b; }
            }
        }
    }
}

// ================= layer-2 input GEMM (R10 proven shape) =================
__global__ __launch_bounds__(352, 1)
void xg2_kernel()
{
    constexpr int BB = 96, K = 140, KP2 = 142, G = 168, NJC = 42, TB = 12;
    extern __shared__ float sm[];
    float* sW = sm;                 // [140][168]
    float* aS = sW + K * G;         // [96][142] duplicated pairs
    float* sb = aS + BB * KP2 * 2;  // [168]
    const int tid = threadIdx.x;
    const size_t row0 = (size_t)blockIdx.x * BB;

    {
        const float4* wsrc = (const float4*)g_w2t;
        float4* wdst = (float4*)sW;
        for (int i = tid; i < K * G / 4; i += 352) wdst[i] = wsrc[i];
    }
    for (int j = tid; j < G; j += 352) sb[j] = g_b2[j];
    {
        const float* src = g_h1 + row0 * K;
        int r = tid / K, c = tid % K;
        for (int q = tid; q < BB * K; q += 352) {
            float v = src[q];
            ((float2*)aS)[r * KP2 + c] = make_float2(v, v);
            r += 2; c += 72; if (c >= K) { c -= K; ++r; }
        }
    }
    __syncthreads();

    if (tid < 336) {
        const int sg = tid / NJC, jc = tid % NJC;
        const u64* arow = ((const u64*)aS) + (size_t)(sg * TB) * KP2;
        const ulonglong2* sWp = (const ulonglong2*)sW;
        float4 b4 = ((const float4*)sb)[jc];
        ulonglong2 binit = *reinterpret_cast<ulonglong2*>(&b4);
        ulonglong2 acc[TB];
        #pragma unroll
        for (int r = 0; r < TB; ++r) acc[r] = binit;

        #pragma unroll 2
        for (int kk = 0; kk < K; kk += 2) {
            ulonglong2 w0 = sWp[kk * NJC + jc];
            ulonglong2 w1 = sWp[(kk + 1) * NJC + jc];
            #pragma unroll
            for (int r = 0; r < TB; ++r) {
                ulonglong2 a = *(const ulonglong2*)(arow + r * KP2 + kk);
                acc[r].x = fma2_(a.x, w0.x, acc[r].x);
                acc[r].y = fma2_(a.x, w0.y, acc[r].y);
                acc[r].x = fma2_(a.y, w1.x, acc[r].x);
                acc[r].y = fma2_(a.y, w1.y, acc[r].y);
            }
        }
        float4* outp = (float4*)(g_xg2 + row0 * G);
        #pragma unroll
        for (int r = 0; r < TB; ++r)
            outp[(sg * TB + r) * NJC + jc] = *reinterpret_cast<float4*>(&acc[r]);
    }
}

// ================= layer 2: recurrent-only LSTM (R10 proven shape: BB=32, 128 blocks) =================
__global__ __launch_bounds__(384, 1)
void lstm2_kernel(const float* __restrict__ Whh_f, const float* __restrict__ Whh_b)
{
    constexpr int H = 21, KPAD = 24, KP2 = 24, G = 84, GP = 96;
    constexpr int NJC = 24, TB = 4, NTH = 384, KH = 12;
    extern __shared__ float sm[];
    float* sW = sm;                 // [24][96] gate-interleaved
    float* gS = sW + KPAD * GP;     // [2][32][96] input gates (double-buffered), team0 rmw
    float* gP = gS + 2 * 32 * GP;   // [32][96] team1 partial
    float* aS = gP + 32 * GP;       // [32][24] duplicated pairs
    float* cS = aS + 32 * KP2 * 2;  // [32][21]

    const int dir = blockIdx.y;
    const float* Whh = dir ? Whh_b : Whh_f;
    const int b0  = blockIdx.x * 32;
    const int tid = threadIdx.x;

    for (int idx = tid; idx < KPAD * GP; idx += NTH) {
        int k = idx / GP, jj = idx % GP;
        float v = 0.f;
        if (k < H && jj < G) {
            int h = jj / 4, gate = jj % 4;
            int j = gate * H + h;
            v = Whh[j * H + k];
        }
        sW[idx] = v;
    }
    for (int idx = tid; idx < 32 * KP2 * 2; idx += NTH) aS[idx] = 0.f;
    for (int idx = tid; idx < 32 * H; idx += NTH) cS[idx] = 0.f;

    const int gb0 = tid / 21, gc0 = tid % 21;
    const int i1 = tid + NTH;
    const int gb1 = i1 / 21, gc1 = i1 % 21;
    const bool v1 = i1 < 672;
    const int ab0 = tid / H, ah0 = tid % H;

    const int ks = tid / 192;
    const int r192 = tid - ks * 192;
    const int sg = r192 / NJC, jc = r192 % NJC;
    const int kbase = ks * KH;
    const u64* arow = ((const u64*)aS) + (size_t)(sg * TB) * KP2;
    const ulonglong2* sWp = (const ulonglong2*)sW;

    int t = dir ? (T_ - 1) : 0;
    const int tstep = dir ? -1 : 1;
    float4 gp0, gp1;
    {
        const float4* src = (const float4*)(g_xg2 + ((size_t)t * B_ + b0) * 168 + dir * 84);
        gp0 = src[gb0 * 42 + gc0];
        if (v1) gp1 = src[gb1 * 42 + gc1];
    }
    __syncthreads();

    for (int s = 0; s < T_; ++s, t += tstep) {
        const int p = s & 1;
        float* gSb = gS + p * 32 * GP;
        float4* gSd = (float4*)gSb;
        gSd[gb0 * 24 + gc0] = gp0;
        if (v1) gSd[gb1 * 24 + gc1] = gp1;
        __syncthreads();
        if (s + 1 < T_) {
            const float4* src = (const float4*)(g_xg2 + ((size_t)(t + tstep) * B_ + b0) * 168 + dir * 84);
            gp0 = src[gb0 * 42 + gc0];
            if (v1) gp1 = src[gb1 * 42 + gc1];
        }
        {
            ulonglong2* dst = (ulonglong2*)(ks ? gP : gSb);
            ulonglong2 acc[TB];
            #pragma unroll
            for (int r = 0; r < TB; ++r) {
                if (ks == 0) acc[r] = ((const ulonglong2*)gSb)[(sg * TB + r) * NJC + jc];
                else         acc[r] = make_ulonglong2(0ull, 0ull);
            }
            #pragma unroll
            for (int kk = 0; kk < KH; kk += 2) {
                const int k = kbase + kk;
                ulonglong2 w0 = sWp[k * NJC + jc];
                ulonglong2 w1 = sWp[(k + 1) * NJC + jc];
                #pragma unroll
                for (int r = 0; r < TB; ++r) {
                    ulonglong2 a = *(const ulonglong2*)(arow + r * KP2 + k);
                    acc[r].x = fma2_(a.x, w0.x, acc[r].x);
                    acc[r].y = fma2_(a.x, w0.y, acc[r].y);
                    acc[r].x = fma2_(a.y, w1.x, acc[r].x);
                    acc[r].y = fma2_(a.y, w1.y, acc[r].y);
                }
            }
            #pragma unroll
            for (int r = 0; r < TB; ++r)
                dst[(sg * TB + r) * NJC + jc] = acc[r];
        }
        __syncthreads();

        {
            float* orow = g_h2 + ((size_t)t * B_ + b0) * (2 * H2_) + dir * H;
            int b = ab0, h = ah0;
            for (int e = tid; e < 32 * H; e += NTH) {
                float4 q0 = ((const float4*)(gSb + b * GP))[h];
                float4 q1 = ((const float4*)(gP + b * GP))[h];
                float gi = q0.x + q1.x;
                float gf = q0.y + q1.y;
                float gg = q0.z + q1.z;
                float go = q0.w + q1.w;
                float c = fsigm(gf) * cS[e] + fsigm(gi) * ftanh_(gg);
                cS[e] = c;
                float hn = fsigm(go) * ftanh_(c);
                ((float2*)aS)[b * KP2 + h] = make_float2(hn, hn);
                orow[b * (2 * H2_) + h] = hn;
                b += 18; h += 6; if (h >= H) { h -= H; ++b; }
            }
        }
    }
}

// ================= dense head, fused output transpose =================
__global__ __launch_bounds__(256)
void dense_kernel(const float* __restrict__ wd1, const float* __restrict__ bd1,
                  const float* __restrict__ wd2, const float* __restrict__ bd2,
                  const float* __restrict__ wo,  const float* __restrict__ bo,
                  float* __restrict__ out)
{
    constexpr int IN = 2 * H2_;   // 42
    constexpr int INP = 43;       // padded pitch (odd -> conflict-free)
    extern __shared__ float sm[];
    float* sIn = sm;                    // [256][43]
    float* s1  = sIn + 256 * INP;       // [30][42]
    float* sb1 = s1 + D1_ * IN;
    float* s2  = sb1 + D1_;             // [20][30]
    float* sb2 = s2 + D2_ * D1_;
    float* sWo = sb2 + D2_;
    float* sBo = sWo + D2_;

    const int tid = threadIdx.x;
    const int t0 = blockIdx.x * 32;     // 11 t-tiles (last partial)
    const int b0 = blockIdx.y * 8;      // 256 b-tiles

    {
        int i = tid / IN, c = tid % IN;
        for (int q = tid; q < 256 * IN; q += 256) {
            int tt = t0 + (i & 31);
            int bb = b0 + (i >> 5);
            float v = 0.f;
            if (tt < T_) v = g_h2[((size_t)tt * B_ + bb) * IN + c];
            sIn[i * INP + c] = v;
            i += 6; c += 4; if (c >= IN) { c -= IN; ++i; }
        }
    }
    for (int i = tid; i < D1_ * IN; i += 256) s1[i] = wd1[i];
    for (int i = tid; i < D2_ * D1_; i += 256) s2[i] = wd2[i];
    if (tid < D1_) sb1[tid] = bd1[tid];
    if (tid < D2_) { sb2[tid] = bd2[tid]; sWo[tid] = wo[tid]; }
    if (tid == 0) sBo[0] = bo[0];
    __syncthreads();

    const float* in = sIn + tid * INP;
    float acc2[D2_];
    #pragma unroll
    for (int k = 0; k < D2_; ++k) acc2[k] = sb2[k];
    #pragma unroll 2
    for (int j = 0; j < D1_; ++j) {
        float v = sb1[j];
        #pragma unroll
        for (int k = 0; k < IN; ++k) v = fmaf(in[k], s1[j * IN + k], v);
        v = fmaxf(v, 0.f);
        #pragma unroll
        for (int k = 0; k < D2_; ++k) acc2[k] = fmaf(v, s2[k * D1_ + j], acc2[k]);
    }
    float y = sBo[0];
    #pragma unroll
    for (int k = 0; k < D2_; ++k) y = fmaf(fmaxf(acc2[k], 0.f), sWo[k], y);

    const int tx = tid & 31, ty = tid >> 5;
    const int t = t0 + tx;
    if (t < T_) out[(size_t)(b0 + ty) * T_ + t] = y;   // coalesced per warp
}

// ---------------- host glue ----------------
extern "C" void kernel_launch(void* const* d_in, const int* in_sizes, int n_in,
                              void* d_out, int out_size)
{
    const float* x      = (const float*)d_in[0];
    const float* w1f_ih = (const float*)d_in[1];
    const float* w1f_hh = (const float*)d_in[2];
    const float* b1f_ih = (const float*)d_in[3];
    const float* b1f_hh = (const float*)d_in[4];
    const float* w1b_ih = (const float*)d_in[5];
    const float* w1b_hh = (const float*)d_in[6];
    const float* b1b_ih = (const float*)d_in[7];
    const float* b1b_hh = (const float*)d_in[8];
    const float* w2f_ih = (const float*)d_in[9];
    const float* w2f_hh = (const float*)d_in[10];
    const float* b2f_ih = (const float*)d_in[11];
    const float* b2f_hh = (const float*)d_in[12];
    const float* w2b_ih = (const float*)d_in[13];
    const float* w2b_hh = (const float*)d_in[14];
    const float* b2b_ih = (const float*)d_in[15];
    const float* b2b_hh = (const float*)d_in[16];
    const float* wd1    = (const float*)d_in[17];
    const float* bd1    = (const float*)d_in[18];
    const float* wd2    = (const float*)d_in[19];
    const float* bd2    = (const float*)d_in[20];
    const float* wo     = (const float*)d_in[21];
    const float* bo     = (const float*)d_in[22];
    float* out = (float*)d_out;

    // lstm1: sW 84*288 + gP 3*28*288 + aS 28*86*2 + cS 28*70
    const int SM1 = (84 * 288 + 3 * 28 * 288 + 28 * 86 * 2 + 28 * 70) * 4;                  // 220640
    const int SMX = (140 * 168 + 96 * 142 * 2 + 168) * 4;                                   // 203808
    const int SM2 = (24 * 96 + 2 * 32 * 96 + 32 * 96 + 32 * 24 * 2 + 32 * 21) * 4;          // 54912
    const int SMD = (256 * 43 + 30 * 42 + 30 + 20 * 30 + 20 + 20 + 1) * 4;                  // ~51932

    cudaFuncSetAttribute(lstm1_kernel, cudaFuncAttributeMaxDynamicSharedMemorySize, SM1);
    cudaFuncSetAttribute(xg2_kernel,   cudaFuncAttributeMaxDynamicSharedMemorySize, SMX);
    cudaFuncSetAttribute(lstm2_kernel, cudaFuncAttributeMaxDynamicSharedMemorySize, SM2);
    cudaFuncSetAttribute(dense_kernel, cudaFuncAttributeMaxDynamicSharedMemorySize, SMD);

    const int TOT = B_ * T_ * F_;
    const int HALF = (TOT + 1) / 2;

    // launches 1-3 (keeps lstm1 as the 4th launch -> profiled by ncu)
    transpose_x<<<(HALF + 255) / 256, 256>>>(x, 0);
    transpose_x<<<(TOT - HALF + 255) / 256, 256>>>(x, HALF);
    prep_w2<<<(168 * 140 + 255) / 256, 256>>>(w2f_ih, w2b_ih, b2f_ih, b2f_hh, b2b_ih, b2b_hh);

    // launch 4: dominant kernel — 148 blocks, 432 threads, 3 K-teams x 2 SG x TB14
    lstm1_kernel<<<dim3((B_ + 27) / 28, 2), 432, SM1>>>(
        w1f_ih, w1f_hh, b1f_ih, b1f_hh,
        w1b_ih, w1b_hh, b1b_ih, b1b_hh);

    // R10 xg2: 128 blocks x 352 threads
    xg2_kernel<<<(T_ * B_) / 96, 352, SMX>>>();

    // R10 lstm2: 64 x 2 = 128 blocks, BB=32
    lstm2_kernel<<<dim3(B_ / 32, 2), 384, SM2>>>(w2f_hh, w2b_hh);

    // fused dense + output transpose: 11 t-tiles x 256 b-tiles
    dense_kernel<<<dim3((T_ + 31) / 32, B_ / 8), 256, SMD>>>(wd1, bd1, wd2, bd2, wo, bo, out);
}

// round 16
// speedup vs baseline: 1.1160x; 1.1160x over previous
#include <cuda_runtime.h>
#include <cstdint>

#define B_  2048
#define T_  336
#define F_  10
#define H1_ 70
#define H2_ 21
#define D1_ 30
#define D2_ 20

typedef unsigned long long u64;

// ---------------- scratch (__device__ globals; no allocations) ----------------
__device__ float g_xT [(size_t)T_ * B_ * F_];          // x transposed [T][B][10]
__device__ float g_h1 [(size_t)T_ * B_ * (2*H1_)];     // layer1 out   [T][B][140]
__device__ float g_xg2[(size_t)T_ * B_ * (8*H2_)];     // layer2 input gates [T][B][168] (gate-interleaved)
__device__ float g_h2 [(size_t)T_ * B_ * (2*H2_)];     // layer2 out   [T][B][42]
__device__ float g_w2t[140 * 168];                     // W2_ih^T packed, both dirs, gate-interleaved
__device__ float g_b2 [168];

// ---------------- packed f32x2 fma ----------------
__device__ __forceinline__ u64 fma2_(u64 a, u64 b, u64 c) {
    u64 d;
    asm("fma.rn.f32x2 %0, %1, %2, %3;" : "=l"(d) : "l"(a), "l"(b), "l"(c));
    return d;
}

// ---------------- activations via HW MUFU.TANH (1 MUFU each, 16-cyc chain) ----------------
__device__ __forceinline__ float ftanh_(float x) {
    float y;
    asm("tanh.approx.f32 %0, %1;" : "=f"(y) : "f"(x));
    return y;
}
__device__ __forceinline__ float fsigm(float x) {
    return fmaf(ftanh_(0.5f * x), 0.5f, 0.5f);
}

// ---------------- transpose x: [B][T][F] -> [T][B][F] (split in halves) ----------------
__global__ void transpose_x(const float* __restrict__ x, int base) {
    int gid = base + blockIdx.x * blockDim.x + threadIdx.x;
    if (gid < B_ * T_ * F_) {
        int f = gid % F_;
        int t = (gid / F_) % T_;
        int b = gid / (F_ * T_);
        g_xT[((size_t)t * B_ + b) * F_ + f] = x[gid];
    }
}

// ---------------- prep: transpose layer-2 input weights to k-major, gate-interleaved ----------------
__global__ void prep_w2(const float* __restrict__ wf, const float* __restrict__ wb,
                        const float* __restrict__ bfi, const float* __restrict__ bfh,
                        const float* __restrict__ bbi, const float* __restrict__ bbh) {
    int i = blockIdx.x * blockDim.x + threadIdx.x;
    if (i < 168 * 140) {
        int jj = i / 140;
        int k  = i % 140;
        int dir = jj / 84, r = jj % 84;
        int h = r / 4, gate = r % 4;
        int j = gate * H2_ + h;
        const float* w = dir ? wb : wf;
        g_w2t[k * 168 + jj] = w[j * 140 + k];
    }
    if (i < 168) {
        int dir = i / 84, r = i % 84;
        int h = r / 4, gate = r % 4;
        int j = gate * H2_ + h;
        g_b2[i] = dir ? (bbi[j] + bbh[j]) : (bfi[j] + bfh[j]);
    }
}

// ================= layer 1: fused-input recurrent LSTM (R10 proven shape) =================
// BB=28 samples/block -> grid 74 x 2 = 148 blocks = one per SM.
// 576 threads = 2 K-teams x (4 SG x 72 chunks), TB=7 rows/thread.
__global__ __launch_bounds__(576, 1)
void lstm1_kernel(const float* __restrict__ Wih_f, const float* __restrict__ Whh_f,
                  const float* __restrict__ bih_f, const float* __restrict__ bhh_f,
                  const float* __restrict__ Wih_b, const float* __restrict__ Whh_b,
                  const float* __restrict__ bih_b, const float* __restrict__ bhh_b)
{
    constexpr int I = 10, H = 70, K = 80, KP2 = 82, G = 280, GP = 288;
    constexpr int NJC = 72, TB = 7, NTH = 576, KH = 40, BB = 28;
    extern __shared__ float sm[];
    float* sW = sm;                    // [80][288] k-major, gate-interleaved
    float* gP = sW + K * GP;           // [2][28][288] partial gates
    float* aS = gP + 2 * BB * GP;      // [28][82] duplicated pairs (float2)
    float* cS = aS + BB * KP2 * 2;     // [28][70]
    float* sb = cS + BB * H;           // [288]

    const int dir = blockIdx.y;
    const float* Wih = dir ? Wih_b : Wih_f;
    const float* Whh = dir ? Whh_b : Whh_f;
    const float* bih = dir ? bih_b : bih_f;
    const float* bhh = dir ? bhh_b : bhh_f;
    const int b0  = blockIdx.x * BB;
    const int tid = threadIdx.x;

    for (int idx = tid; idx < K * GP; idx += NTH) {
        int k = idx / GP, jj = idx % GP;
        float v = 0.f;
        if (jj < G) {
            int h = jj / 4, gate = jj % 4;
            int j = gate * H + h;
            v = (k < I) ? Wih[j * I + k] : Whh[j * H + (k - I)];
        }
        sW[idx] = v;
    }
    for (int jj = tid; jj < GP; jj += NTH) {
        float v = 0.f;
        if (jj < G) {
            int h = jj / 4, gate = jj % 4;
            int j = gate * H + h;
            v = bih[j] + bhh[j];
        }
        sb[jj] = v;
    }
    for (int idx = tid; idx < BB * KP2 * 2; idx += NTH) aS[idx] = 0.f;
    for (int idx = tid; idx < BB * H; idx += NTH) cS[idx] = 0.f;

    const bool xp = tid < BB * I;
    const int xb0 = tid / I, xk0 = tid % I;
    const bool xval = xp && (b0 + xb0 < B_);   // tail-chunk guard
    const int ab0 = tid / H, ah0 = tid % H;

    const int ks = tid / 288;           // K-team
    const int r288 = tid - ks * 288;
    const int sg = r288 / NJC, jc = r288 % NJC;
    const int kbase = ks * KH;
    const u64* arow = ((const u64*)aS) + (size_t)(sg * TB) * KP2;
    const ulonglong2* sWp = (const ulonglong2*)sW;
    ulonglong2* gPd = ((ulonglong2*)(gP + ks * BB * GP));

    int t = dir ? (T_ - 1) : 0;
    const int tstep = dir ? -1 : 1;
    float xp0 = 0.f;
    if (xval) xp0 = g_xT[((size_t)t * B_ + b0) * I + tid];
    __syncthreads();

    for (int s = 0; s < T_; ++s, t += tstep) {
        if (xp) ((float2*)aS)[xb0 * KP2 + xk0] = make_float2(xp0, xp0);
        __syncthreads();
        if (xval && s + 1 < T_)
            xp0 = g_xT[((size_t)(t + tstep) * B_ + b0) * I + tid];

        {
            float4 b4 = make_float4(0.f, 0.f, 0.f, 0.f);
            if (ks == 0) b4 = ((const float4*)sb)[jc];
            ulonglong2 binit = *reinterpret_cast<ulonglong2*>(&b4);
            ulonglong2 acc[TB];
            #pragma unroll
            for (int r = 0; r < TB; ++r) acc[r] = binit;

            #pragma unroll 4
            for (int kk = 0; kk < KH; kk += 2) {
                const int k = kbase + kk;
                ulonglong2 w0 = sWp[k * NJC + jc];
                ulonglong2 w1 = sWp[(k + 1) * NJC + jc];
                #pragma unroll
                for (int r = 0; r < TB; ++r) {
                    ulonglong2 a = *(const ulonglong2*)(arow + r * KP2 + k);
                    acc[r].x = fma2_(a.x, w0.x, acc[r].x);
                    acc[r].y = fma2_(a.x, w0.y, acc[r].y);
                    acc[r].x = fma2_(a.y, w1.x, acc[r].x);
                    acc[r].y = fma2_(a.y, w1.y, acc[r].y);
                }
            }
            #pragma unroll
            for (int r = 0; r < TB; ++r) gPd[(sg * TB + r) * NJC + jc] = acc[r];
        }
        __syncthreads();

        {
            float* orow = g_h1 + ((size_t)t * B_ + b0) * (2 * H1_) + dir * H;
            int b = ab0, h = ah0;
            for (int e = tid; e < BB * H; e += NTH) {
                float4 q0 = ((const float4*)(gP + b * GP))[h];
                float4 q1 = ((const float4*)(gP + BB * GP + b * GP))[h];
                float gi = q0.x + q1.x;
                float gf = q0.y + q1.y;
                float gg = q0.z + q1.z;
                float go = q0.w + q1.w;
                float c = fsigm(gf) * cS[e] + fsigm(gi) * ftanh_(gg);
                cS[e] = c;
                float hn = fsigm(go) * ftanh_(c);
                ((float2*)aS)[b * KP2 + I + h] = make_float2(hn, hn);
                if (b0 + b < B_) orow[b * (2 * H1_) + h] = hn;
                b += 8; h += 16; if (h >= H) { h -= H; ++b; }
            }
        }
    }
}

// ================= layer-2 input GEMM (R10 proven shape) =================
__global__ __launch_bounds__(352, 1)
void xg2_kernel()
{
    constexpr int BB = 96, K = 140, KP2 = 142, G = 168, NJC = 42, TB = 12;
    extern __shared__ float sm[];
    float* sW = sm;                 // [140][168]
    float* aS = sW + K * G;         // [96][142] duplicated pairs
    float* sb = aS + BB * KP2 * 2;  // [168]
    const int tid = threadIdx.x;
    const size_t row0 = (size_t)blockIdx.x * BB;

    {
        const float4* wsrc = (const float4*)g_w2t;
        float4* wdst = (float4*)sW;
        for (int i = tid; i < K * G / 4; i += 352) wdst[i] = wsrc[i];
    }
    for (int j = tid; j < G; j += 352) sb[j] = g_b2[j];
    {
        const float* src = g_h1 + row0 * K;
        int r = tid / K, c = tid % K;
        for (int q = tid; q < BB * K; q += 352) {
            float v = src[q];
            ((float2*)aS)[r * KP2 + c] = make_float2(v, v);
            r += 2; c += 72; if (c >= K) { c -= K; ++r; }
        }
    }
    __syncthreads();

    if (tid < 336) {
        const int sg = tid / NJC, jc = tid % NJC;
        const u64* arow = ((const u64*)aS) + (size_t)(sg * TB) * KP2;
        const ulonglong2* sWp = (const ulonglong2*)sW;
        float4 b4 = ((const float4*)sb)[jc];
        ulonglong2 binit = *reinterpret_cast<ulonglong2*>(&b4);
        ulonglong2 acc[TB];
        #pragma unroll
        for (int r = 0; r < TB; ++r) acc[r] = binit;

        #pragma unroll 2
        for (int kk = 0; kk < K; kk += 2) {
            ulonglong2 w0 = sWp[kk * NJC + jc];
            ulonglong2 w1 = sWp[(kk + 1) * NJC + jc];
            #pragma unroll
            for (int r = 0; r < TB; ++r) {
                ulonglong2 a = *(const ulonglong2*)(arow + r * KP2 + kk);
                acc[r].x = fma2_(a.x, w0.x, acc[r].x);
                acc[r].y = fma2_(a.x, w0.y, acc[r].y);
                acc[r].x = fma2_(a.y, w1.x, acc[r].x);
                acc[r].y = fma2_(a.y, w1.y, acc[r].y);
            }
        }
        float4* outp = (float4*)(g_xg2 + row0 * G);
        #pragma unroll
        for (int r = 0; r < TB; ++r)
            outp[(sg * TB + r) * NJC + jc] = *reinterpret_cast<float4*>(&acc[r]);
    }
}

// ================= layer 2: recurrent-only LSTM (R10 proven shape: BB=32, 128 blocks) =================
__global__ __launch_bounds__(384, 1)
void lstm2_kernel(const float* __restrict__ Whh_f, const float* __restrict__ Whh_b)
{
    constexpr int H = 21, KPAD = 24, KP2 = 24, G = 84, GP = 96;
    constexpr int NJC = 24, TB = 4, NTH = 384, KH = 12;
    extern __shared__ float sm[];
    float* sW = sm;                 // [24][96] gate-interleaved
    float* gS = sW + KPAD * GP;     // [2][32][96] input gates (double-buffered), team0 rmw
    float* gP = gS + 2 * 32 * GP;   // [32][96] team1 partial
    float* aS = gP + 32 * GP;       // [32][24] duplicated pairs
    float* cS = aS + 32 * KP2 * 2;  // [32][21]

    const int dir = blockIdx.y;
    const float* Whh = dir ? Whh_b : Whh_f;
    const int b0  = blockIdx.x * 32;
    const int tid = threadIdx.x;

    for (int idx = tid; idx < KPAD * GP; idx += NTH) {
        int k = idx / GP, jj = idx % GP;
        float v = 0.f;
        if (k < H && jj < G) {
            int h = jj / 4, gate = jj % 4;
            int j = gate * H + h;
            v = Whh[j * H + k];
        }
        sW[idx] = v;
    }
    for (int idx = tid; idx < 32 * KP2 * 2; idx += NTH) aS[idx] = 0.f;
    for (int idx = tid; idx < 32 * H; idx += NTH) cS[idx] = 0.f;

    const int gb0 = tid / 21, gc0 = tid % 21;
    const int i1 = tid + NTH;
    const int gb1 = i1 / 21, gc1 = i1 % 21;
    const bool v1 = i1 < 672;
    const int ab0 = tid / H, ah0 = tid % H;

    const int ks = tid / 192;
    const int r192 = tid - ks * 192;
    const int sg = r192 / NJC, jc = r192 % NJC;
    const int kbase = ks * KH;
    const u64* arow = ((const u64*)aS) + (size_t)(sg * TB) * KP2;
    const ulonglong2* sWp = (const ulonglong2*)sW;

    int t = dir ? (T_ - 1) : 0;
    const int tstep = dir ? -1 : 1;
    float4 gp0, gp1;
    {
        const float4* src = (const float4*)(g_xg2 + ((size_t)t * B_ + b0) * 168 + dir * 84);
        gp0 = src[gb0 * 42 + gc0];
        if (v1) gp1 = src[gb1 * 42 + gc1];
    }
    __syncthreads();

    for (int s = 0; s < T_; ++s, t += tstep) {
        const int p = s & 1;
        float* gSb = gS + p * 32 * GP;
        float4* gSd = (float4*)gSb;
        gSd[gb0 * 24 + gc0] = gp0;
        if (v1) gSd[gb1 * 24 + gc1] = gp1;
        __syncthreads();
        if (s + 1 < T_) {
            const float4* src = (const float4*)(g_xg2 + ((size_t)(t + tstep) * B_ + b0) * 168 + dir * 84);
            gp0 = src[gb0 * 42 + gc0];
            if (v1) gp1 = src[gb1 * 42 + gc1];
        }
        {
            ulonglong2* dst = (ulonglong2*)(ks ? gP : gSb);
            ulonglong2 acc[TB];
            #pragma unroll
            for (int r = 0; r < TB; ++r) {
                if (ks == 0) acc[r] = ((const ulonglong2*)gSb)[(sg * TB + r) * NJC + jc];
                else         acc[r] = make_ulonglong2(0ull, 0ull);
            }
            #pragma unroll
            for (int kk = 0; kk < KH; kk += 2) {
                const int k = kbase + kk;
                ulonglong2 w0 = sWp[k * NJC + jc];
                ulonglong2 w1 = sWp[(k + 1) * NJC + jc];
                #pragma unroll
                for (int r = 0; r < TB; ++r) {
                    ulonglong2 a = *(const ulonglong2*)(arow + r * KP2 + k);
                    acc[r].x = fma2_(a.x, w0.x, acc[r].x);
                    acc[r].y = fma2_(a.x, w0.y, acc[r].y);
                    acc[r].x = fma2_(a.y, w1.x, acc[r].x);
                    acc[r].y = fma2_(a.y, w1.y, acc[r].y);
                }
            }
            #pragma unroll
            for (int r = 0; r < TB; ++r)
                dst[(sg * TB + r) * NJC + jc] = acc[r];
        }
        __syncthreads();

        {
            float* orow = g_h2 + ((size_t)t * B_ + b0) * (2 * H2_) + dir * H;
            int b = ab0, h = ah0;
            for (int e = tid; e < 32 * H; e += NTH) {
                float4 q0 = ((const float4*)(gSb + b * GP))[h];
                float4 q1 = ((const float4*)(gP + b * GP))[h];
                float gi = q0.x + q1.x;
                float gf = q0.y + q1.y;
                float gg = q0.z + q1.z;
                float go = q0.w + q1.w;
                float c = fsigm(gf) * cS[e] + fsigm(gi) * ftanh_(gg);
                cS[e] = c;
                float hn = fsigm(go) * ftanh_(c);
                ((float2*)aS)[b * KP2 + h] = make_float2(hn, hn);
                orow[b * (2 * H2_) + h] = hn;
                b += 18; h += 6; if (h >= H) { h -= H; ++b; }
            }
        }
    }
}

// ================= dense head, fused output transpose =================
__global__ __launch_bounds__(256)
void dense_kernel(const float* __restrict__ wd1, const float* __restrict__ bd1,
                  const float* __restrict__ wd2, const float* __restrict__ bd2,
                  const float* __restrict__ wo,  const float* __restrict__ bo,
                  float* __restrict__ out)
{
    constexpr int IN = 2 * H2_;   // 42
    constexpr int INP = 43;       // padded pitch (odd -> conflict-free)
    extern __shared__ float sm[];
    float* sIn = sm;                    // [256][43]
    float* s1  = sIn + 256 * INP;       // [30][42]
    float* sb1 = s1 + D1_ * IN;
    float* s2  = sb1 + D1_;             // [20][30]
    float* sb2 = s2 + D2_ * D1_;
    float* sWo = sb2 + D2_;
    float* sBo = sWo + D2_;

    const int tid = threadIdx.x;
    const int t0 = blockIdx.x * 32;     // 11 t-tiles (last partial)
    const int b0 = blockIdx.y * 8;      // 256 b-tiles

    {
        int i = tid / IN, c = tid % IN;
        for (int q = tid; q < 256 * IN; q += 256) {
            int tt = t0 + (i & 31);
            int bb = b0 + (i >> 5);
            float v = 0.f;
            if (tt < T_) v = g_h2[((size_t)tt * B_ + bb) * IN + c];
            sIn[i * INP + c] = v;
            i += 6; c += 4; if (c >= IN) { c -= IN; ++i; }
        }
    }
    for (int i = tid; i < D1_ * IN; i += 256) s1[i] = wd1[i];
    for (int i = tid; i < D2_ * D1_; i += 256) s2[i] = wd2[i];
    if (tid < D1_) sb1[tid] = bd1[tid];
    if (tid < D2_) { sb2[tid] = bd2[tid]; sWo[tid] = wo[tid]; }
    if (tid == 0) sBo[0] = bo[0];
    __syncthreads();

    const float* in = sIn + tid * INP;
    float acc2[D2_];
    #pragma unroll
    for (int k = 0; k < D2_; ++k) acc2[k] = sb2[k];
    #pragma unroll 2
    for (int j = 0; j < D1_; ++j) {
        float v = sb1[j];
        #pragma unroll
        for (int k = 0; k < IN; ++k) v = fmaf(in[k], s1[j * IN + k], v);
        v = fmaxf(v, 0.f);
        #pragma unroll
        for (int k = 0; k < D2_; ++k) acc2[k] = fmaf(v, s2[k * D1_ + j], acc2[k]);
    }
    float y = sBo[0];
    #pragma unroll
    for (int k = 0; k < D2_; ++k) y = fmaf(fmaxf(acc2[k], 0.f), sWo[k], y);

    const int tx = tid & 31, ty = tid >> 5;
    const int t = t0 + tx;
    if (t < T_) out[(size_t)(b0 + ty) * T_ + t] = y;   // coalesced per warp
}

// ---------------- host glue ----------------
extern "C" void kernel_launch(void* const* d_in, const int* in_sizes, int n_in,
                              void* d_out, int out_size)
{
    const float* x      = (const float*)d_in[0];
    const float* w1f_ih = (const float*)d_in[1];
    const float* w1f_hh = (const float*)d_in[2];
    const float* b1f_ih = (const float*)d_in[3];
    const float* b1f_hh = (const float*)d_in[4];
    const float* w1b_ih = (const float*)d_in[5];
    const float* w1b_hh = (const float*)d_in[6];
    const float* b1b_ih = (const float*)d_in[7];
    const float* b1b_hh = (const float*)d_in[8];
    const float* w2f_ih = (const float*)d_in[9];
    const float* w2f_hh = (const float*)d_in[10];
    const float* b2f_ih = (const float*)d_in[11];
    const float* b2f_hh = (const float*)d_in[12];
    const float* w2b_ih = (const float*)d_in[13];
    const float* w2b_hh = (const float*)d_in[14];
    const float* b2b_ih = (const float*)d_in[15];
    const float* b2b_hh = (const float*)d_in[16];
    const float* wd1    = (const float*)d_in[17];
    const float* bd1    = (const float*)d_in[18];
    const float* wd2    = (const float*)d_in[19];
    const float* bd2    = (const float*)d_in[20];
    const float* wo     = (const float*)d_in[21];
    const float* bo     = (const float*)d_in[22];
    float* out = (float*)d_out;

    const int SM1 = (80 * 288 + 2 * 28 * 288 + 28 * 82 * 2 + 28 * 70 + 288) * 4;            // 184032
    const int SMX = (140 * 168 + 96 * 142 * 2 + 168) * 4;                                   // 203808
    const int SM2 = (24 * 96 + 2 * 32 * 96 + 32 * 96 + 32 * 24 * 2 + 32 * 21) * 4;          // 54912
    const int SMD = (256 * 43 + 30 * 42 + 30 + 20 * 30 + 20 + 20 + 1) * 4;                  // ~51932

    cudaFuncSetAttribute(lstm1_kernel, cudaFuncAttributeMaxDynamicSharedMemorySize, SM1);
    cudaFuncSetAttribute(xg2_kernel,   cudaFuncAttributeMaxDynamicSharedMemorySize, SMX);
    cudaFuncSetAttribute(lstm2_kernel, cudaFuncAttributeMaxDynamicSharedMemorySize, SM2);
    cudaFuncSetAttribute(dense_kernel, cudaFuncAttributeMaxDynamicSharedMemorySize, SMD);

    const int TOT = B_ * T_ * F_;
    const int HALF = (TOT + 1) / 2;

    // launches 1-3 (keeps lstm1 as the 4th launch -> profiled by ncu)
    transpose_x<<<(HALF + 255) / 256, 256>>>(x, 0);
    transpose_x<<<(TOT - HALF + 255) / 256, 256>>>(x, HALF);
    prep_w2<<<(168 * 140 + 255) / 256, 256>>>(w2f_ih, w2b_ih, b2f_ih, b2f_hh, b2b_ih, b2b_hh);

    // launch 4: dominant kernel — 148 blocks, 576 threads, TB=7 (proven shape)
    lstm1_kernel<<<dim3((B_ + 27) / 28, 2), 576, SM1>>>(
        w1f_ih, w1f_hh, b1f_ih, b1f_hh,
        w1b_ih, w1b_hh, b1b_ih, b1b_hh);

    // R10 xg2: 128 blocks x 352 threads
    xg2_kernel<<<(T_ * B_) / 96, 352, SMX>>>();

    // R10 lstm2: 64 x 2 = 128 blocks, BB=32
    lstm2_kernel<<<dim3(B_ / 32, 2), 384, SM2>>>(w2f_hh, w2b_hh);

    // fused dense + output transpose: 11 t-tiles x 256 b-tiles
    dense_kernel<<<dim3((T_ + 31) / 32, B_ / 8), 256, SMD>>>(wd1, bd1, wd2, bd2, wo, bo, out);
}